// round 15
// baseline (speedup 1.0000x reference)
#include <cuda_runtime.h>
#include <cuda_fp16.h>
#include <cstdint>

// y = x @ w + b  (exact collapse of the memristor model; G_off / K_V / k_g all
// cancel).  2-term fp16-split GEMM on mma.sync tensor cores:
//   y = xh@wh + xl@wh   (x = xh+xl EXACT: xh = mask to 10 mantissa bits,
//   fp16-representable; only w-rounding error ~2e-4)
// Grid 256 = 8 row-blocks(16) x 32 col-blocks(16), 2 CTAs/SM (97KB smem each).
// Each CTA does FULL K=1024: 16 warps take 64-k slices; smem tree reduce.
// No scratch, no atomics, no inter-CTA coordination.

#define NIN 1024
#define NOUT 512
#define BATCH 128
#define NTHR 512

#define XST 1032   // halfs/row: A-frag read banks 4g+tq -> conflict-free
#define WST 1034   // halfs/row
#define RST 272    // reduce: 16x17 floats per warp

#define OFF_XHI 0
#define OFF_XLO (OFF_XHI + 16 * XST)            // 16512
#define OFF_W   (OFF_XLO + 16 * XST)            // 33024
#define SMEM_HALFS (OFF_W + 16 * WST)           // 49568 halfs = 99136 B
#define SMEM_BYTES (SMEM_HALFS * 2)

__device__ __forceinline__ uint32_t packh(float a, float b) {
    __half2 h = __floats2half2_rn(a, b);        // a -> low 16 bits
    return *reinterpret_cast<uint32_t*>(&h);
}
__device__ __forceinline__ uint64_t pack64(uint32_t lo, uint32_t hi) {
    uint64_t r; asm("mov.b64 %0, {%1, %2};" : "=l"(r) : "r"(lo), "r"(hi)); return r;
}
__device__ __forceinline__ float trunc10(float x) {   // top 10 mantissa bits
    return __uint_as_float(__float_as_uint(x) & 0xFFFFE000u);
}
__device__ __forceinline__ void mma_f16(float* c, const uint32_t* a, const uint32_t* b) {
    asm volatile(
        "mma.sync.aligned.m16n8k16.row.col.f32.f16.f16.f32 "
        "{%0,%1,%2,%3}, {%4,%5,%6,%7}, {%8,%9}, {%0,%1,%2,%3};"
        : "+f"(c[0]), "+f"(c[1]), "+f"(c[2]), "+f"(c[3])
        : "r"(a[0]), "r"(a[1]), "r"(a[2]), "r"(a[3]), "r"(b[0]), "r"(b[1]));
}

__global__ __launch_bounds__(NTHR, 2) void fused_kernel(
    const float* __restrict__ X, const float* __restrict__ W,
    const float* __restrict__ B, float* __restrict__ out)
{
    extern __shared__ __half sm[];
    __half* Xhi = sm + OFF_XHI;
    __half* Xlo = sm + OFF_XLO;
    __half* Wn  = sm + OFF_W;

    const int t = threadIdx.x, bid = blockIdx.x;
    const int warp = t >> 5, lane = t & 31;
    const int g  = lane >> 2;          // group row 0..7
    const int tq = lane & 3;           // thread-in-group 0..3
    const int r0 = (bid >> 5) * 16;    // row block 0..7
    const int c0 = (bid & 31) * 16;    // col block 0..31

    // ---- fill X: 16 rows x 1024 k.  xh = 10-bit truncation (fp16-exact),
    //      xl = x - xh (exact).  16*256 float4 slots = 8 iters. ----
    #pragma unroll
    for (int i = 0; i < 8; ++i) {
        int idx = t + i * NTHR;                 // 0..4095
        int kq = idx & 255, row = idx >> 8;     // row 0..15
        float4 xv = *reinterpret_cast<const float4*>(&X[(r0 + row) * NIN + 4 * kq]);
        float h0 = trunc10(xv.x), h1 = trunc10(xv.y);
        float h2 = trunc10(xv.z), h3 = trunc10(xv.w);
        int e = row * XST + 4 * kq;             // byte 2064*row+8*kq: 8B-aligned
        *reinterpret_cast<uint64_t*>(&Xhi[e]) = pack64(packh(h0, h1), packh(h2, h3));
        *reinterpret_cast<uint64_t*>(&Xlo[e]) =
            pack64(packh(xv.x - h0, xv.y - h1), packh(xv.z - h2, xv.w - h3));
    }
    // ---- fill W: 1024 k x 16 n -> [n][k] fp16 pairs (round-to-nearest).
    //      512 kp * 16 n = 8192 slots = 16 iters. ----
    #pragma unroll
    for (int i = 0; i < 16; ++i) {
        int idx = t + i * NTHR;                 // 0..8191
        int n = idx & 15, kp = idx >> 4;        // kp 0..511
        float w0 = W[(2 * kp) * NOUT + c0 + n];
        float w1 = W[(2 * kp + 1) * NOUT + c0 + n];
        *reinterpret_cast<uint32_t*>(&Wn[n * WST + 2 * kp]) = packh(w0, w1);
    }
    __syncthreads();

    // ---- compute: warp = FULL 16x16 tile, k slice [warp*64, warp*64+64) ----
    float acc[2][4];
    #pragma unroll
    for (int j = 0; j < 2; ++j)
        #pragma unroll
        for (int q = 0; q < 4; ++q) acc[j][q] = 0.f;

    const int arow0 = g * XST;
    const int arow1 = arow0 + 8 * XST;

    #pragma unroll
    for (int kk = 0; kk < 4; ++kk) {
        const int kb = warp * 64 + kk * 16 + 2 * tq;
        uint32_t ah[4], al[4];
        ah[0] = *reinterpret_cast<const uint32_t*>(&Xhi[arow0 + kb]);
        ah[1] = *reinterpret_cast<const uint32_t*>(&Xhi[arow1 + kb]);
        ah[2] = *reinterpret_cast<const uint32_t*>(&Xhi[arow0 + kb + 8]);
        ah[3] = *reinterpret_cast<const uint32_t*>(&Xhi[arow1 + kb + 8]);
        al[0] = *reinterpret_cast<const uint32_t*>(&Xlo[arow0 + kb]);
        al[1] = *reinterpret_cast<const uint32_t*>(&Xlo[arow1 + kb]);
        al[2] = *reinterpret_cast<const uint32_t*>(&Xlo[arow0 + kb + 8]);
        al[3] = *reinterpret_cast<const uint32_t*>(&Xlo[arow1 + kb + 8]);

        uint32_t bh[2][2];
        #pragma unroll
        for (int j = 0; j < 2; ++j) {
            const int brow = (8 * j + g) * WST;
            bh[j][0] = *reinterpret_cast<const uint32_t*>(&Wn[brow + kb]);
            bh[j][1] = *reinterpret_cast<const uint32_t*>(&Wn[brow + kb + 8]);
        }
        #pragma unroll
        for (int j = 0; j < 2; ++j) mma_f16(acc[j], ah, bh[j]);
        #pragma unroll
        for (int j = 0; j < 2; ++j) mma_f16(acc[j], al, bh[j]);
    }

    // ---- intra-CTA reduce over the 16 k-slices (smem, fixed order) ----
    __syncthreads();                            // tiles no longer read
    float* red  = reinterpret_cast<float*>(sm); // 16 warps x 272 floats
    float* red2 = red + 16 * RST;               // 256 floats
    #pragma unroll
    for (int j = 0; j < 2; ++j)
        #pragma unroll
        for (int q = 0; q < 4; ++q) {
            int row = g + 8 * (q >> 1);
            int col = 8 * j + 2 * tq + (q & 1);
            red[warp * RST + row * 17 + col] = acc[j][q];
        }
    __syncthreads();

    // half the threads sum warps 0-7, other half warps 8-15; then combine.
    {
        int o = t & 255;                        // 0..255 = 16x16 outputs
        int row = o >> 4, col = o & 15;
        int wbase = (t >> 8) * 8;               // 0 or 8
        float v[8];
        #pragma unroll
        for (int w = 0; w < 8; ++w)
            v[w] = red[(wbase + w) * RST + row * 17 + col];
        #pragma unroll
        for (int s = 1; s < 8; s <<= 1)
            #pragma unroll
            for (int c = 0; c < 8; c += 2 * s)
                v[c] += v[c + s];
        if (t >= 256) red2[o] = v[0];
        __syncthreads();
        if (t < 256)
            out[(r0 + row) * NOUT + c0 + col] = (v[0] + red2[o]) + B[c0 + col];
    }
}

extern "C" void kernel_launch(void* const* d_in, const int* in_sizes, int n_in,
                              void* d_out, int out_size)
{
    const float* X = (const float*)d_in[0];  // (128, 1024)
    const float* W = (const float*)d_in[1];  // (1024, 512)
    const float* B = (const float*)d_in[2];  // (512,)
    float* out = (float*)d_out;              // (128, 512)

    cudaFuncSetAttribute(fused_kernel, cudaFuncAttributeMaxDynamicSharedMemorySize, SMEM_BYTES);
    fused_kernel<<<256, NTHR, SMEM_BYTES>>>(X, W, B, out);
}